// round 1
// baseline (speedup 1.0000x reference)
#include <cuda_runtime.h>
#include <cuda_bf16.h>
#include <math.h>

// Problem constants
#define DIMC   1152
#define NH     8
#define KVH    2
#define HD     144
#define BSZ    4
#define SEQ    2048
#define MROWS  (BSZ*SEQ)          // 8192
#define KVOUT  (2*KVH*HD)         // 576
#define HALF   (HD/2)             // 72

// ---------------- scratch (device globals; no allocation allowed) ----------
__device__ float g_q   [(size_t)MROWS * DIMC];   // x@wq^T+bq
__device__ float g_kv  [(size_t)MROWS * KVOUT];  // x@wkv^T+bkv
__device__ float g_qr  [(size_t)BSZ * NH  * SEQ * HD]; // rope(Q) [b][h][s][d]
__device__ float g_kr  [(size_t)BSZ * KVH * SEQ * HD]; // rope(K) [b][kvh][s][d]
__device__ float g_v   [(size_t)BSZ * KVH * SEQ * HD]; // V       [b][kvh][s][d]
__device__ float g_attn[(size_t)MROWS * DIMC];   // attention output [b,s][h*144+d]

// ---------------- SGEMM: C[M,N] = A[M,K] @ B[N,K]^T + bias ------------------
// BM=BN=128, BK=8, 256 threads, 8x8 microtile.
__global__ __launch_bounds__(256, 2)
void sgemm_bt(const float* __restrict__ A, const float* __restrict__ B,
              const float* __restrict__ bias, float* __restrict__ C,
              int M, int N, int K)
{
    __shared__ float As[8][128];
    __shared__ float Bs[8][128];

    const int bx = blockIdx.x;            // N tile
    const int by = blockIdx.y;            // M tile
    const int tid = threadIdx.x;
    const int tcol = tid & 15;
    const int trow = tid >> 4;

    const int ar = tid >> 1;              // 0..127
    const int ac = (tid & 1) * 4;         // 0 or 4

    const float* Ab = A + (size_t)(by * 128) * K;
    const float* Bb = B + (size_t)(bx * 128) * K;
    const int brow_g = bx * 128 + ar;     // global B row (output column)

    float acc[8][8];
#pragma unroll
    for (int i = 0; i < 8; i++)
#pragma unroll
        for (int j = 0; j < 8; j++) acc[i][j] = 0.f;

    for (int k0 = 0; k0 < K; k0 += 8) {
        float4 av = *(const float4*)(Ab + (size_t)ar * K + k0 + ac);
        float4 bv = make_float4(0.f, 0.f, 0.f, 0.f);
        if (brow_g < N) bv = *(const float4*)(Bb + (size_t)ar * K + k0 + ac);

        __syncthreads();
        As[ac + 0][ar] = av.x; As[ac + 1][ar] = av.y;
        As[ac + 2][ar] = av.z; As[ac + 3][ar] = av.w;
        Bs[ac + 0][ar] = bv.x; Bs[ac + 1][ar] = bv.y;
        Bs[ac + 2][ar] = bv.z; Bs[ac + 3][ar] = bv.w;
        __syncthreads();

#pragma unroll
        for (int kk = 0; kk < 8; kk++) {
            float a[8], b[8];
            *(float4*)(a)     = *(const float4*)&As[kk][trow * 8];
            *(float4*)(a + 4) = *(const float4*)&As[kk][trow * 8 + 4];
            *(float4*)(b)     = *(const float4*)&Bs[kk][tcol * 8];
            *(float4*)(b + 4) = *(const float4*)&Bs[kk][tcol * 8 + 4];
#pragma unroll
            for (int i = 0; i < 8; i++)
#pragma unroll
                for (int j = 0; j < 8; j++)
                    acc[i][j] = fmaf(a[i], b[j], acc[i][j]);
        }
    }

    const int row0 = by * 128 + trow * 8;
    const int col0 = bx * 128 + tcol * 8;
#pragma unroll
    for (int i = 0; i < 8; i++) {
        float* Crow = C + (size_t)(row0 + i) * N;
#pragma unroll
        for (int j = 0; j < 8; j++) {
            int cc = col0 + j;
            if (cc < N) Crow[cc] = acc[i][j] + bias[cc];
        }
    }
}

// ---------------- RoPE ------------------------------------------------------
__global__ void rope_q_kernel(const float* __restrict__ Q,
                              const float* __restrict__ fc, const float* __restrict__ fs,
                              float* __restrict__ qr)
{
    int idx = blockIdx.x * blockDim.x + threadIdx.x;
    const int total = BSZ * SEQ * NH * HALF;
    if (idx >= total) return;
    int i = idx % HALF;
    int h = (idx / HALF) % NH;
    int s = (idx / (HALF * NH)) % SEQ;
    int b = idx / (HALF * NH * SEQ);

    size_t base = (size_t)(b * SEQ + s) * DIMC + h * HD;
    float q0 = Q[base + 2 * i];
    float q1 = Q[base + 2 * i + 1];
    float c = fc[s * HALF + i];
    float sn = fs[s * HALF + i];
    size_t ob = ((size_t)(b * NH + h) * SEQ + s) * HD;
    qr[ob + 2 * i]     = q0 * c - q1 * sn;
    qr[ob + 2 * i + 1] = q0 * sn + q1 * c;
}

__global__ void rope_kv_kernel(const float* __restrict__ KV,
                               const float* __restrict__ fc, const float* __restrict__ fs,
                               float* __restrict__ kr, float* __restrict__ vv)
{
    int idx = blockIdx.x * blockDim.x + threadIdx.x;
    const int total = BSZ * SEQ * KVH * HALF;
    if (idx >= total) return;
    int i = idx % HALF;
    int kvh = (idx / HALF) % KVH;
    int s = (idx / (HALF * KVH)) % SEQ;
    int b = idx / (HALF * KVH * SEQ);

    size_t m = (size_t)(b * SEQ + s);
    size_t kbase = m * KVOUT + kvh * HD;
    size_t vbase = m * KVOUT + KVH * HD + kvh * HD;

    float k0 = KV[kbase + 2 * i];
    float k1 = KV[kbase + 2 * i + 1];
    float c = fc[s * HALF + i];
    float sn = fs[s * HALF + i];

    size_t ob = ((size_t)(b * KVH + kvh) * SEQ + s) * HD;
    kr[ob + 2 * i]     = k0 * c - k1 * sn;
    kr[ob + 2 * i + 1] = k0 * sn + k1 * c;
    vv[ob + 2 * i]     = KV[vbase + 2 * i];
    vv[ob + 2 * i + 1] = KV[vbase + 2 * i + 1];
}

// ---------------- Flash attention (fp32, causal, GQA) ----------------------
// One CTA per (64-query tile, b*h). 256 threads (16x16), 4x4 S microtile,
// 4x9 O microtile. Online softmax, 16-lane shfl row reductions.
#define LDK 145   // padded row stride for sQ/sK/sV
#define LDP 68    // padded row stride for sP

__global__ __launch_bounds__(256, 1)
void flash_attn(const float* __restrict__ qr, const float* __restrict__ kr,
                const float* __restrict__ vv, float* __restrict__ out)
{
    extern __shared__ float sm[];
    float* sQ = sm;                 // [64][145]
    float* sK = sQ + 64 * LDK;      // [64][145]
    float* sV = sK + 64 * LDK;      // [64][145]
    float* sP = sV + 64 * LDK;      // [64][68]

    const int qt = blockIdx.x;      // query tile 0..31
    const int bh = blockIdx.y;      // b*8+h
    const int b = bh >> 3;
    const int h = bh & 7;
    const int kvh = h >> 2;         // GROUPS=4

    const int tid = threadIdx.x;
    const int tx = tid & 15;
    const int ty = tid >> 4;

    // load Q tile
    const float* qbase = qr + ((size_t)bh * SEQ + qt * 64) * HD;
    for (int e = tid; e < 64 * HD; e += 256) {
        int r = e / HD, c = e % HD;
        sQ[r * LDK + c] = qbase[e];
    }

    float m_i[4], l_i[4], o[4][9];
#pragma unroll
    for (int i = 0; i < 4; i++) {
        m_i[i] = -INFINITY; l_i[i] = 0.f;
#pragma unroll
        for (int j = 0; j < 9; j++) o[i][j] = 0.f;
    }

    const float* kb = kr + (size_t)(b * KVH + kvh) * SEQ * HD;
    const float* vb = vv + (size_t)(b * KVH + kvh) * SEQ * HD;
    const float scale = 0.083333333333333329f;  // 1/sqrt(144)

    for (int kt = 0; kt <= qt; kt++) {
        __syncthreads();   // previous PV done with sK/sV
        const float* kk = kb + (size_t)kt * 64 * HD;
        const float* vk = vb + (size_t)kt * 64 * HD;
        for (int e = tid; e < 64 * HD; e += 256) {
            int r = e / HD, c = e % HD;
            sK[r * LDK + c] = kk[e];
            sV[r * LDK + c] = vk[e];
        }
        __syncthreads();

        // S = Q @ K^T  (4x4 per thread)
        float s[4][4];
#pragma unroll
        for (int i = 0; i < 4; i++)
#pragma unroll
            for (int j = 0; j < 4; j++) s[i][j] = 0.f;

        for (int d = 0; d < HD; d++) {
            float qv[4], kv4[4];
#pragma unroll
            for (int i = 0; i < 4; i++) qv[i] = sQ[(ty * 4 + i) * LDK + d];
#pragma unroll
            for (int j = 0; j < 4; j++) kv4[j] = sK[(tx * 4 + j) * LDK + d];
#pragma unroll
            for (int i = 0; i < 4; i++)
#pragma unroll
                for (int j = 0; j < 4; j++)
                    s[i][j] = fmaf(qv[i], kv4[j], s[i][j]);
        }

        // scale + causal mask (only diagonal tile needs masking)
        if (kt == qt) {
#pragma unroll
            for (int i = 0; i < 4; i++)
#pragma unroll
                for (int j = 0; j < 4; j++) {
                    float v = s[i][j] * scale;
                    if (tx * 4 + j > ty * 4 + i) v += -1e9f;
                    s[i][j] = v;
                }
        } else {
#pragma unroll
            for (int i = 0; i < 4; i++)
#pragma unroll
                for (int j = 0; j < 4; j++) s[i][j] *= scale;
        }

        // online softmax per row (16 lanes per row share via shfl)
#pragma unroll
        for (int i = 0; i < 4; i++) {
            float mt = s[i][0];
#pragma unroll
            for (int j = 1; j < 4; j++) mt = fmaxf(mt, s[i][j]);
#pragma unroll
            for (int off = 1; off < 16; off <<= 1)
                mt = fmaxf(mt, __shfl_xor_sync(0xffffffffu, mt, off));
            float mn = fmaxf(m_i[i], mt);
            float corr = __expf(m_i[i] - mn);
            float ls = 0.f;
#pragma unroll
            for (int j = 0; j < 4; j++) {
                float p = __expf(s[i][j] - mn);
                s[i][j] = p;
                ls += p;
            }
#pragma unroll
            for (int off = 1; off < 16; off <<= 1)
                ls += __shfl_xor_sync(0xffffffffu, ls, off);
            l_i[i] = l_i[i] * corr + ls;
            m_i[i] = mn;
#pragma unroll
            for (int j = 0; j < 9; j++) o[i][j] *= corr;
            *(float4*)&sP[(ty * 4 + i) * LDP + tx * 4] =
                make_float4(s[i][0], s[i][1], s[i][2], s[i][3]);
        }
        __syncthreads();

        // O += P @ V   (4 rows x 9 cols per thread; col c = tx + 16*j)
#pragma unroll 4
        for (int t = 0; t < 64; t++) {
            float pr[4];
#pragma unroll
            for (int i = 0; i < 4; i++) pr[i] = sP[(ty * 4 + i) * LDP + t];
            float vr[9];
#pragma unroll
            for (int j = 0; j < 9; j++) vr[j] = sV[t * LDK + tx + 16 * j];
#pragma unroll
            for (int i = 0; i < 4; i++)
#pragma unroll
                for (int j = 0; j < 9; j++)
                    o[i][j] = fmaf(pr[i], vr[j], o[i][j]);
        }
    }

    // epilogue: normalize and write [b, s, h*144+d]
    float* ob = out + ((size_t)(b * SEQ + qt * 64) * NH + h) * HD;
#pragma unroll
    for (int i = 0; i < 4; i++) {
        float inv = 1.f / l_i[i];
        float* row = ob + (size_t)(ty * 4 + i) * (NH * HD);
#pragma unroll
        for (int j = 0; j < 9; j++)
            row[tx + 16 * j] = o[i][j] * inv;
    }
}

#define FLASH_SMEM ((3 * 64 * LDK + 64 * LDP) * (int)sizeof(float))

// ---------------- launcher --------------------------------------------------
extern "C" void kernel_launch(void* const* d_in, const int* in_sizes, int n_in,
                              void* d_out, int out_size)
{
    const float* x   = (const float*)d_in[0];
    const float* wq  = (const float*)d_in[1];
    const float* bq  = (const float*)d_in[2];
    const float* wkv = (const float*)d_in[3];
    const float* bkv = (const float*)d_in[4];
    const float* wo  = (const float*)d_in[5];
    const float* bo  = (const float*)d_in[6];
    const float* fc  = (const float*)d_in[7];
    const float* fs  = (const float*)d_in[8];
    float* out = (float*)d_out;

    float *gq, *gkv, *gqr, *gkr, *gv, *gat;
    cudaGetSymbolAddress((void**)&gq,  g_q);
    cudaGetSymbolAddress((void**)&gkv, g_kv);
    cudaGetSymbolAddress((void**)&gqr, g_qr);
    cudaGetSymbolAddress((void**)&gkr, g_kr);
    cudaGetSymbolAddress((void**)&gv,  g_v);
    cudaGetSymbolAddress((void**)&gat, g_attn);

    cudaFuncSetAttribute(flash_attn, cudaFuncAttributeMaxDynamicSharedMemorySize,
                         FLASH_SMEM);

    // Q and KV projections
    sgemm_bt<<<dim3(DIMC / 128, MROWS / 128), 256>>>(x, wq,  bq,  gq,  MROWS, DIMC,  DIMC);
    sgemm_bt<<<dim3((KVOUT + 127) / 128, MROWS / 128), 256>>>(x, wkv, bkv, gkv, MROWS, KVOUT, DIMC);

    // RoPE + layout rearrange
    {
        int tq = BSZ * SEQ * NH * HALF;
        rope_q_kernel<<<(tq + 255) / 256, 256>>>(gq, fc, fs, gqr);
        int tkv = BSZ * SEQ * KVH * HALF;
        rope_kv_kernel<<<(tkv + 255) / 256, 256>>>(gkv, fc, fs, gkr, gv);
    }

    // attention
    flash_attn<<<dim3(SEQ / 64, BSZ * NH), 256, FLASH_SMEM>>>(gqr, gkr, gv, gat);

    // output projection
    sgemm_bt<<<dim3(DIMC / 128, MROWS / 128), 256>>>(gat, wo, bo, out, MROWS, DIMC, DIMC);
}

// round 2
// speedup vs baseline: 1.4130x; 1.4130x over previous
#include <cuda_runtime.h>
#include <cuda_bf16.h>
#include <math.h>
#include <stdint.h>

// Problem constants
#define DIMC   1152
#define NH     8
#define KVH    2
#define HD     144
#define BSZ    4
#define SEQ    2048
#define MROWS  (BSZ*SEQ)          // 8192
#define KVOUT  (2*KVH*HD)         // 576
#define HALF   (HD/2)             // 72
#define K2DIM  (DIMC/2)           // 576 packed bf16x2 per row

// ---------------- scratch (device globals; no allocation allowed) ----------
__device__ float g_q   [(size_t)MROWS * DIMC];
__device__ float g_kv  [(size_t)MROWS * KVOUT];
__device__ float g_qr  [(size_t)BSZ * NH  * SEQ * HD];
__device__ float g_kr  [(size_t)BSZ * KVH * SEQ * HD];
__device__ float g_v   [(size_t)BSZ * KVH * SEQ * HD];
__device__ float g_attn[(size_t)MROWS * DIMC];

// packed bf16x2 hi/lo splits
__device__ uint32_t g_xh [(size_t)MROWS * K2DIM];
__device__ uint32_t g_xl [(size_t)MROWS * K2DIM];
__device__ uint32_t g_wqh[(size_t)DIMC  * K2DIM];
__device__ uint32_t g_wql[(size_t)DIMC  * K2DIM];
__device__ uint32_t g_wkh[(size_t)KVOUT * K2DIM];
__device__ uint32_t g_wkl[(size_t)KVOUT * K2DIM];
__device__ uint32_t g_woh[(size_t)DIMC  * K2DIM];
__device__ uint32_t g_wol[(size_t)DIMC  * K2DIM];
__device__ uint32_t g_ah [(size_t)MROWS * K2DIM];
__device__ uint32_t g_al [(size_t)MROWS * K2DIM];

// ---------------- fp32 -> (hi, lo) packed bf16x2 ---------------------------
__global__ void split_bf16(const float* __restrict__ src,
                           uint32_t* __restrict__ hi, uint32_t* __restrict__ lo,
                           int n2)
{
    int i = blockIdx.x * blockDim.x + threadIdx.x;
    if (i >= n2) return;
    float2 v = ((const float2*)src)[i];
    __nv_bfloat162 h = __floats2bfloat162_rn(v.x, v.y);
    float hx = __bfloat162float(h.x), hy = __bfloat162float(h.y);
    __nv_bfloat162 l = __floats2bfloat162_rn(v.x - hx, v.y - hy);
    hi[i] = *reinterpret_cast<uint32_t*>(&h);
    lo[i] = *reinterpret_cast<uint32_t*>(&l);
}

// ---------------- bf16 mma helper ------------------------------------------
__device__ __forceinline__ void mma16816(float* c, const uint32_t* a, const uint32_t* b)
{
    asm volatile(
        "mma.sync.aligned.m16n8k16.row.col.f32.bf16.bf16.f32 "
        "{%0,%1,%2,%3}, {%4,%5,%6,%7}, {%8,%9}, {%0,%1,%2,%3};\n"
        : "+f"(c[0]), "+f"(c[1]), "+f"(c[2]), "+f"(c[3])
        : "r"(a[0]), "r"(a[1]), "r"(a[2]), "r"(a[3]), "r"(b[0]), "r"(b[1]));
}

// ---------------- split-bf16 GEMM: C[M,N] = A[M,K]@B[N,K]^T + bias ---------
// Operands pre-split into hi/lo packed bf16x2 (K/2 uint32 per row).
// BM=BN=128, BK=32 (16 kp), 256 threads, warp tile 64x32.
#define KPS 20   // smem row stride in uint32 (16 kp + 4 pad) -> conflict-free frags

__global__ __launch_bounds__(256, 2)
void gemm_bf3(const uint32_t* __restrict__ Ahg, const uint32_t* __restrict__ Alg,
              const uint32_t* __restrict__ Bhg, const uint32_t* __restrict__ Blg,
              const float* __restrict__ bias, float* __restrict__ C,
              int M, int N, int K2)
{
    __shared__ uint32_t Ah[128 * KPS], Al[128 * KPS];
    __shared__ uint32_t Bh[128 * KPS], Bl[128 * KPS];

    const int bx = blockIdx.x, by = blockIdx.y;
    const int tid = threadIdx.x;
    const int warp = tid >> 5, lane = tid & 31;
    const int wm = (warp & 1) * 64;        // warp M offset in tile
    const int wn = (warp >> 1) * 32;       // warp N offset in tile
    const int lr = lane >> 2, lc = lane & 3;

    // staging: each thread owns (row = tid/2, 8 kp starting at (tid&1)*8)
    const int srow = tid >> 1;
    const int sk = (tid & 1) * 8;
    const uint32_t* agh = Ahg + (size_t)(by * 128 + srow) * K2 + sk;
    const uint32_t* agl = Alg + (size_t)(by * 128 + srow) * K2 + sk;
    const int brow = bx * 128 + srow;
    const bool bok = brow < N;
    const uint32_t* bgh = Bhg + (size_t)(bok ? brow : 0) * K2 + sk;
    const uint32_t* bgl = Blg + (size_t)(bok ? brow : 0) * K2 + sk;

    float acc[4][4][4];
#pragma unroll
    for (int i = 0; i < 4; i++)
#pragma unroll
        for (int j = 0; j < 4; j++)
#pragma unroll
            for (int t = 0; t < 4; t++) acc[i][j][t] = 0.f;

    const uint4 zero4 = make_uint4(0u, 0u, 0u, 0u);

    for (int k0 = 0; k0 < K2; k0 += 16) {
        uint4 a0 = *(const uint4*)(agh + k0);
        uint4 a1 = *(const uint4*)(agh + k0 + 4);
        uint4 l0 = *(const uint4*)(agl + k0);
        uint4 l1 = *(const uint4*)(agl + k0 + 4);
        uint4 b0 = bok ? *(const uint4*)(bgh + k0)     : zero4;
        uint4 b1 = bok ? *(const uint4*)(bgh + k0 + 4) : zero4;
        uint4 m0 = bok ? *(const uint4*)(bgl + k0)     : zero4;
        uint4 m1 = bok ? *(const uint4*)(bgl + k0 + 4) : zero4;

        __syncthreads();
        *(uint4*)&Ah[srow * KPS + sk]     = a0;
        *(uint4*)&Ah[srow * KPS + sk + 4] = a1;
        *(uint4*)&Al[srow * KPS + sk]     = l0;
        *(uint4*)&Al[srow * KPS + sk + 4] = l1;
        *(uint4*)&Bh[srow * KPS + sk]     = b0;
        *(uint4*)&Bh[srow * KPS + sk + 4] = b1;
        *(uint4*)&Bl[srow * KPS + sk]     = m0;
        *(uint4*)&Bl[srow * KPS + sk + 4] = m1;
        __syncthreads();

#pragma unroll
        for (int kk = 0; kk < 16; kk += 8) {
            uint32_t bh[4][2], bl[4][2];
#pragma unroll
            for (int j = 0; j < 4; j++) {
                int nr = (wn + j * 8 + lr) * KPS;
                bh[j][0] = Bh[nr + kk + lc];
                bh[j][1] = Bh[nr + kk + 4 + lc];
                bl[j][0] = Bl[nr + kk + lc];
                bl[j][1] = Bl[nr + kk + 4 + lc];
            }
#pragma unroll
            for (int i = 0; i < 4; i++) {
                int r0 = (wm + i * 16 + lr) * KPS;
                int r1 = (wm + i * 16 + 8 + lr) * KPS;
                uint32_t ah[4], al[4];
                ah[0] = Ah[r0 + kk + lc];
                ah[1] = Ah[r1 + kk + lc];
                ah[2] = Ah[r0 + kk + 4 + lc];
                ah[3] = Ah[r1 + kk + 4 + lc];
                al[0] = Al[r0 + kk + lc];
                al[1] = Al[r1 + kk + lc];
                al[2] = Al[r0 + kk + 4 + lc];
                al[3] = Al[r1 + kk + 4 + lc];
#pragma unroll
                for (int j = 0; j < 4; j++) {
                    mma16816(acc[i][j], ah, bh[j]);
                    mma16816(acc[i][j], ah, bl[j]);
                    mma16816(acc[i][j], al, bh[j]);
                }
            }
        }
    }

    // epilogue
#pragma unroll
    for (int i = 0; i < 4; i++) {
        int r0 = by * 128 + wm + i * 16 + lr;
#pragma unroll
        for (int j = 0; j < 4; j++) {
            int c0 = bx * 128 + wn + j * 8 + lc * 2;
            if (c0 < N) {
                float2 bb = *(const float2*)&bias[c0];
                float2 v0 = make_float2(acc[i][j][0] + bb.x, acc[i][j][1] + bb.y);
                float2 v1 = make_float2(acc[i][j][2] + bb.x, acc[i][j][3] + bb.y);
                *(float2*)&C[(size_t)r0 * N + c0]       = v0;
                *(float2*)&C[(size_t)(r0 + 8) * N + c0] = v1;
            }
        }
    }
}

// ---------------- RoPE ------------------------------------------------------
__global__ void rope_q_kernel(const float* __restrict__ Q,
                              const float* __restrict__ fc, const float* __restrict__ fs,
                              float* __restrict__ qr)
{
    int idx = blockIdx.x * blockDim.x + threadIdx.x;
    const int total = BSZ * SEQ * NH * HALF;
    if (idx >= total) return;
    int i = idx % HALF;
    int h = (idx / HALF) % NH;
    int s = (idx / (HALF * NH)) % SEQ;
    int b = idx / (HALF * NH * SEQ);

    size_t base = (size_t)(b * SEQ + s) * DIMC + h * HD;
    float q0 = Q[base + 2 * i];
    float q1 = Q[base + 2 * i + 1];
    float c = fc[s * HALF + i];
    float sn = fs[s * HALF + i];
    size_t ob = ((size_t)(b * NH + h) * SEQ + s) * HD;
    qr[ob + 2 * i]     = q0 * c - q1 * sn;
    qr[ob + 2 * i + 1] = q0 * sn + q1 * c;
}

__global__ void rope_kv_kernel(const float* __restrict__ KV,
                               const float* __restrict__ fc, const float* __restrict__ fs,
                               float* __restrict__ kr, float* __restrict__ vv)
{
    int idx = blockIdx.x * blockDim.x + threadIdx.x;
    const int total = BSZ * SEQ * KVH * HALF;
    if (idx >= total) return;
    int i = idx % HALF;
    int kvh = (idx / HALF) % KVH;
    int s = (idx / (HALF * KVH)) % SEQ;
    int b = idx / (HALF * KVH * SEQ);

    size_t m = (size_t)(b * SEQ + s);
    size_t kbase = m * KVOUT + kvh * HD;
    size_t vbase = m * KVOUT + KVH * HD + kvh * HD;

    float k0 = KV[kbase + 2 * i];
    float k1 = KV[kbase + 2 * i + 1];
    float c = fc[s * HALF + i];
    float sn = fs[s * HALF + i];

    size_t ob = ((size_t)(b * KVH + kvh) * SEQ + s) * HD;
    kr[ob + 2 * i]     = k0 * c - k1 * sn;
    kr[ob + 2 * i + 1] = k0 * sn + k1 * c;
    vv[ob + 2 * i]     = KV[vbase + 2 * i];
    vv[ob + 2 * i + 1] = KV[vbase + 2 * i + 1];
}

// ---------------- Flash attention (fp32, causal, GQA) ----------------------
#define LDK 145
#define LDP 68

__global__ __launch_bounds__(256, 1)
void flash_attn(const float* __restrict__ qr, const float* __restrict__ kr,
                const float* __restrict__ vv, float* __restrict__ out)
{
    extern __shared__ float sm[];
    float* sQ = sm;
    float* sK = sQ + 64 * LDK;
    float* sV = sK + 64 * LDK;
    float* sP = sV + 64 * LDK;

    const int qt = (gridDim.x - 1) - blockIdx.x;   // heavy tiles first
    const int bh = blockIdx.y;
    const int b = bh >> 3;
    const int h = bh & 7;
    const int kvh = h >> 2;

    const int tid = threadIdx.x;
    const int tx = tid & 15;
    const int ty = tid >> 4;

    const float* qbase = qr + ((size_t)bh * SEQ + qt * 64) * HD;
    for (int e = tid; e < 64 * HD; e += 256) {
        int r = e / HD, c = e % HD;
        sQ[r * LDK + c] = qbase[e];
    }

    float m_i[4], l_i[4], o[4][9];
#pragma unroll
    for (int i = 0; i < 4; i++) {
        m_i[i] = -INFINITY; l_i[i] = 0.f;
#pragma unroll
        for (int j = 0; j < 9; j++) o[i][j] = 0.f;
    }

    const float* kb = kr + (size_t)(b * KVH + kvh) * SEQ * HD;
    const float* vb = vv + (size_t)(b * KVH + kvh) * SEQ * HD;
    const float scale = 0.083333333333333329f;

    for (int kt = 0; kt <= qt; kt++) {
        __syncthreads();
        const float* kk = kb + (size_t)kt * 64 * HD;
        const float* vk = vb + (size_t)kt * 64 * HD;
        for (int e = tid; e < 64 * HD; e += 256) {
            int r = e / HD, c = e % HD;
            sK[r * LDK + c] = kk[e];
            sV[r * LDK + c] = vk[e];
        }
        __syncthreads();

        float s[4][4];
#pragma unroll
        for (int i = 0; i < 4; i++)
#pragma unroll
            for (int j = 0; j < 4; j++) s[i][j] = 0.f;

        for (int d = 0; d < HD; d++) {
            float qv[4], kv4[4];
#pragma unroll
            for (int i = 0; i < 4; i++) qv[i] = sQ[(ty * 4 + i) * LDK + d];
#pragma unroll
            for (int j = 0; j < 4; j++) kv4[j] = sK[(tx * 4 + j) * LDK + d];
#pragma unroll
            for (int i = 0; i < 4; i++)
#pragma unroll
                for (int j = 0; j < 4; j++)
                    s[i][j] = fmaf(qv[i], kv4[j], s[i][j]);
        }

        if (kt == qt) {
#pragma unroll
            for (int i = 0; i < 4; i++)
#pragma unroll
                for (int j = 0; j < 4; j++) {
                    float v = s[i][j] * scale;
                    if (tx * 4 + j > ty * 4 + i) v += -1e9f;
                    s[i][j] = v;
                }
        } else {
#pragma unroll
            for (int i = 0; i < 4; i++)
#pragma unroll
                for (int j = 0; j < 4; j++) s[i][j] *= scale;
        }

#pragma unroll
        for (int i = 0; i < 4; i++) {
            float mt = s[i][0];
#pragma unroll
            for (int j = 1; j < 4; j++) mt = fmaxf(mt, s[i][j]);
#pragma unroll
            for (int off = 1; off < 16; off <<= 1)
                mt = fmaxf(mt, __shfl_xor_sync(0xffffffffu, mt, off));
            float mn = fmaxf(m_i[i], mt);
            float corr = __expf(m_i[i] - mn);
            float ls = 0.f;
#pragma unroll
            for (int j = 0; j < 4; j++) {
                float p = __expf(s[i][j] - mn);
                s[i][j] = p;
                ls += p;
            }
#pragma unroll
            for (int off = 1; off < 16; off <<= 1)
                ls += __shfl_xor_sync(0xffffffffu, ls, off);
            l_i[i] = l_i[i] * corr + ls;
            m_i[i] = mn;
#pragma unroll
            for (int j = 0; j < 9; j++) o[i][j] *= corr;
            *(float4*)&sP[(ty * 4 + i) * LDP + tx * 4] =
                make_float4(s[i][0], s[i][1], s[i][2], s[i][3]);
        }
        __syncthreads();

#pragma unroll 4
        for (int t = 0; t < 64; t++) {
            float pr[4];
#pragma unroll
            for (int i = 0; i < 4; i++) pr[i] = sP[(ty * 4 + i) * LDP + t];
            float vr[9];
#pragma unroll
            for (int j = 0; j < 9; j++) vr[j] = sV[t * LDK + tx + 16 * j];
#pragma unroll
            for (int i = 0; i < 4; i++)
#pragma unroll
                for (int j = 0; j < 9; j++)
                    o[i][j] = fmaf(pr[i], vr[j], o[i][j]);
        }
    }

    float* ob = out + ((size_t)(b * SEQ + qt * 64) * NH + h) * HD;
#pragma unroll
    for (int i = 0; i < 4; i++) {
        float inv = 1.f / l_i[i];
        float* row = ob + (size_t)(ty * 4 + i) * (NH * HD);
#pragma unroll
        for (int j = 0; j < 9; j++)
            row[tx + 16 * j] = o[i][j] * inv;
    }
}

#define FLASH_SMEM ((3 * 64 * LDK + 64 * LDP) * (int)sizeof(float))

// ---------------- launcher --------------------------------------------------
extern "C" void kernel_launch(void* const* d_in, const int* in_sizes, int n_in,
                              void* d_out, int out_size)
{
    const float* x   = (const float*)d_in[0];
    const float* wq  = (const float*)d_in[1];
    const float* bq  = (const float*)d_in[2];
    const float* wkv = (const float*)d_in[3];
    const float* bkv = (const float*)d_in[4];
    const float* wo  = (const float*)d_in[5];
    const float* bo  = (const float*)d_in[6];
    const float* fc  = (const float*)d_in[7];
    const float* fs  = (const float*)d_in[8];
    float* out = (float*)d_out;

    float *gq, *gkv, *gqr, *gkr, *gv, *gat;
    uint32_t *xh, *xl, *wqh, *wql, *wkh, *wkl, *woh, *wol, *ah, *al;
    cudaGetSymbolAddress((void**)&gq,  g_q);
    cudaGetSymbolAddress((void**)&gkv, g_kv);
    cudaGetSymbolAddress((void**)&gqr, g_qr);
    cudaGetSymbolAddress((void**)&gkr, g_kr);
    cudaGetSymbolAddress((void**)&gv,  g_v);
    cudaGetSymbolAddress((void**)&gat, g_attn);
    cudaGetSymbolAddress((void**)&xh,  g_xh);
    cudaGetSymbolAddress((void**)&xl,  g_xl);
    cudaGetSymbolAddress((void**)&wqh, g_wqh);
    cudaGetSymbolAddress((void**)&wql, g_wql);
    cudaGetSymbolAddress((void**)&wkh, g_wkh);
    cudaGetSymbolAddress((void**)&wkl, g_wkl);
    cudaGetSymbolAddress((void**)&woh, g_woh);
    cudaGetSymbolAddress((void**)&wol, g_wol);
    cudaGetSymbolAddress((void**)&ah,  g_ah);
    cudaGetSymbolAddress((void**)&al,  g_al);

    cudaFuncSetAttribute(flash_attn, cudaFuncAttributeMaxDynamicSharedMemorySize,
                         FLASH_SMEM);

    // split inputs into bf16 hi/lo
    {
        int nx = MROWS * K2DIM;
        split_bf16<<<(nx + 255) / 256, 256>>>(x, xh, xl, nx);
        int nq = DIMC * K2DIM;
        split_bf16<<<(nq + 255) / 256, 256>>>(wq, wqh, wql, nq);
        int nk = KVOUT * K2DIM;
        split_bf16<<<(nk + 255) / 256, 256>>>(wkv, wkh, wkl, nk);
        split_bf16<<<(nq + 255) / 256, 256>>>(wo, woh, wol, nq);
    }

    // Q and KV projections (tensor-core split-bf16)
    gemm_bf3<<<dim3(DIMC / 128, MROWS / 128), 256>>>(xh, xl, wqh, wql, bq, gq,
                                                     MROWS, DIMC, K2DIM);
    gemm_bf3<<<dim3((KVOUT + 127) / 128, MROWS / 128), 256>>>(xh, xl, wkh, wkl, bkv, gkv,
                                                              MROWS, KVOUT, K2DIM);

    // RoPE + layout rearrange
    {
        int tq = BSZ * SEQ * NH * HALF;
        rope_q_kernel<<<(tq + 255) / 256, 256>>>(gq, fc, fs, gqr);
        int tkv = BSZ * SEQ * KVH * HALF;
        rope_kv_kernel<<<(tkv + 255) / 256, 256>>>(gkv, fc, fs, gkr, gv);
    }

    // attention
    flash_attn<<<dim3(SEQ / 64, BSZ * NH), 256, FLASH_SMEM>>>(gqr, gkr, gv, gat);

    // output projection
    {
        int na = MROWS * K2DIM;
        split_bf16<<<(na + 255) / 256, 256>>>(gat, ah, al, na);
    }
    gemm_bf3<<<dim3(DIMC / 128, MROWS / 128), 256>>>(ah, al, woh, wol, bo, out,
                                                     MROWS, DIMC, K2DIM);
}

// round 3
// speedup vs baseline: 2.3612x; 1.6711x over previous
#include <cuda_runtime.h>
#include <cuda_bf16.h>
#include <math.h>
#include <stdint.h>

// Problem constants
#define DIMC   1152
#define NH     8
#define KVH    2
#define HD     144
#define BSZ    4
#define SEQ    2048
#define MROWS  (BSZ*SEQ)          // 8192
#define KVOUT  (2*KVH*HD)         // 576
#define HALF   (HD/2)             // 72
#define K2DIM  (DIMC/2)           // 576
#define KP     72                 // bf16x2 pairs per head row
#define TPH    (SEQ/2)            // seq pairs for V^T

// ---------------- scratch (device globals) ----------------------------------
__device__ float g_q   [(size_t)MROWS * DIMC];
__device__ float g_kv  [(size_t)MROWS * KVOUT];
__device__ float g_attn[(size_t)MROWS * DIMC];

// GEMM operand splits
__device__ uint32_t g_xh [(size_t)MROWS * K2DIM];
__device__ uint32_t g_xl [(size_t)MROWS * K2DIM];
__device__ uint32_t g_wqh[(size_t)DIMC  * K2DIM];
__device__ uint32_t g_wql[(size_t)DIMC  * K2DIM];
__device__ uint32_t g_wkh[(size_t)KVOUT * K2DIM];
__device__ uint32_t g_wkl[(size_t)KVOUT * K2DIM];
__device__ uint32_t g_woh[(size_t)DIMC  * K2DIM];
__device__ uint32_t g_wol[(size_t)DIMC  * K2DIM];
__device__ uint32_t g_ah [(size_t)MROWS * K2DIM];
__device__ uint32_t g_al [(size_t)MROWS * K2DIM];

// attention operand splits (packed bf16x2)
__device__ uint32_t g_qh[(size_t)BSZ*NH *SEQ*KP];
__device__ uint32_t g_ql[(size_t)BSZ*NH *SEQ*KP];
__device__ uint32_t g_kh[(size_t)BSZ*KVH*SEQ*KP];
__device__ uint32_t g_kl[(size_t)BSZ*KVH*SEQ*KP];
__device__ uint32_t g_vh[(size_t)BSZ*KVH*HD*TPH];   // V^T, pairs along s
__device__ uint32_t g_vl[(size_t)BSZ*KVH*HD*TPH];

// ---------------- helpers ----------------------------------------------------
__device__ __forceinline__ void split2(float x, float y, uint32_t& hi, uint32_t& lo)
{
    __nv_bfloat162 h = __floats2bfloat162_rn(x, y);
    float hx = __bfloat162float(h.x), hy = __bfloat162float(h.y);
    __nv_bfloat162 l = __floats2bfloat162_rn(x - hx, y - hy);
    hi = *reinterpret_cast<uint32_t*>(&h);
    lo = *reinterpret_cast<uint32_t*>(&l);
}

__device__ __forceinline__ void mma16816(float* c, const uint32_t* a, const uint32_t* b)
{
    asm volatile(
        "mma.sync.aligned.m16n8k16.row.col.f32.bf16.bf16.f32 "
        "{%0,%1,%2,%3}, {%4,%5,%6,%7}, {%8,%9}, {%0,%1,%2,%3};\n"
        : "+f"(c[0]), "+f"(c[1]), "+f"(c[2]), "+f"(c[3])
        : "r"(a[0]), "r"(a[1]), "r"(a[2]), "r"(a[3]), "r"(b[0]), "r"(b[1]));
}

// ---------------- fp32 -> (hi, lo) packed bf16x2 ----------------------------
__global__ void split_bf16(const float* __restrict__ src,
                           uint32_t* __restrict__ hi, uint32_t* __restrict__ lo,
                           int n2)
{
    int i = blockIdx.x * blockDim.x + threadIdx.x;
    if (i >= n2) return;
    float2 v = ((const float2*)src)[i];
    split2(v.x, v.y, hi[i], lo[i]);
}

// ---------------- split-bf16 GEMM (as in R2) --------------------------------
#define KPS 20

__global__ __launch_bounds__(256, 2)
void gemm_bf3(const uint32_t* __restrict__ Ahg, const uint32_t* __restrict__ Alg,
              const uint32_t* __restrict__ Bhg, const uint32_t* __restrict__ Blg,
              const float* __restrict__ bias, float* __restrict__ C,
              int M, int N, int K2)
{
    __shared__ uint32_t Ah[128 * KPS], Al[128 * KPS];
    __shared__ uint32_t Bh[128 * KPS], Bl[128 * KPS];

    const int bx = blockIdx.x, by = blockIdx.y;
    const int tid = threadIdx.x;
    const int warp = tid >> 5, lane = tid & 31;
    const int wm = (warp & 1) * 64;
    const int wn = (warp >> 1) * 32;
    const int lr = lane >> 2, lc = lane & 3;

    const int srow = tid >> 1;
    const int sk = (tid & 1) * 8;
    const uint32_t* agh = Ahg + (size_t)(by * 128 + srow) * K2 + sk;
    const uint32_t* agl = Alg + (size_t)(by * 128 + srow) * K2 + sk;
    const int brow = bx * 128 + srow;
    const bool bok = brow < N;
    const uint32_t* bgh = Bhg + (size_t)(bok ? brow : 0) * K2 + sk;
    const uint32_t* bgl = Blg + (size_t)(bok ? brow : 0) * K2 + sk;

    float acc[4][4][4];
#pragma unroll
    for (int i = 0; i < 4; i++)
#pragma unroll
        for (int j = 0; j < 4; j++)
#pragma unroll
            for (int t = 0; t < 4; t++) acc[i][j][t] = 0.f;

    const uint4 zero4 = make_uint4(0u, 0u, 0u, 0u);

    for (int k0 = 0; k0 < K2; k0 += 16) {
        uint4 a0 = *(const uint4*)(agh + k0);
        uint4 a1 = *(const uint4*)(agh + k0 + 4);
        uint4 l0 = *(const uint4*)(agl + k0);
        uint4 l1 = *(const uint4*)(agl + k0 + 4);
        uint4 b0 = bok ? *(const uint4*)(bgh + k0)     : zero4;
        uint4 b1 = bok ? *(const uint4*)(bgh + k0 + 4) : zero4;
        uint4 m0 = bok ? *(const uint4*)(bgl + k0)     : zero4;
        uint4 m1 = bok ? *(const uint4*)(bgl + k0 + 4) : zero4;

        __syncthreads();
        *(uint4*)&Ah[srow * KPS + sk]     = a0;
        *(uint4*)&Ah[srow * KPS + sk + 4] = a1;
        *(uint4*)&Al[srow * KPS + sk]     = l0;
        *(uint4*)&Al[srow * KPS + sk + 4] = l1;
        *(uint4*)&Bh[srow * KPS + sk]     = b0;
        *(uint4*)&Bh[srow * KPS + sk + 4] = b1;
        *(uint4*)&Bl[srow * KPS + sk]     = m0;
        *(uint4*)&Bl[srow * KPS + sk + 4] = m1;
        __syncthreads();

#pragma unroll
        for (int kk = 0; kk < 16; kk += 8) {
            uint32_t bh[4][2], bl[4][2];
#pragma unroll
            for (int j = 0; j < 4; j++) {
                int nr = (wn + j * 8 + lr) * KPS;
                bh[j][0] = Bh[nr + kk + lc];
                bh[j][1] = Bh[nr + kk + 4 + lc];
                bl[j][0] = Bl[nr + kk + lc];
                bl[j][1] = Bl[nr + kk + 4 + lc];
            }
#pragma unroll
            for (int i = 0; i < 4; i++) {
                int r0 = (wm + i * 16 + lr) * KPS;
                int r1 = (wm + i * 16 + 8 + lr) * KPS;
                uint32_t ah[4], al[4];
                ah[0] = Ah[r0 + kk + lc];
                ah[1] = Ah[r1 + kk + lc];
                ah[2] = Ah[r0 + kk + 4 + lc];
                ah[3] = Ah[r1 + kk + 4 + lc];
                al[0] = Al[r0 + kk + lc];
                al[1] = Al[r1 + kk + lc];
                al[2] = Al[r0 + kk + 4 + lc];
                al[3] = Al[r1 + kk + 4 + lc];
#pragma unroll
                for (int j = 0; j < 4; j++) {
                    mma16816(acc[i][j], ah, bh[j]);
                    mma16816(acc[i][j], ah, bl[j]);
                    mma16816(acc[i][j], al, bh[j]);
                }
            }
        }
    }

#pragma unroll
    for (int i = 0; i < 4; i++) {
        int r0 = by * 128 + wm + i * 16 + lr;
#pragma unroll
        for (int j = 0; j < 4; j++) {
            int c0 = bx * 128 + wn + j * 8 + lc * 2;
            if (c0 < N) {
                float2 bb = *(const float2*)&bias[c0];
                float2 v0 = make_float2(acc[i][j][0] + bb.x, acc[i][j][1] + bb.y);
                float2 v1 = make_float2(acc[i][j][2] + bb.x, acc[i][j][3] + bb.y);
                *(float2*)&C[(size_t)r0 * N + c0]       = v0;
                *(float2*)&C[(size_t)(r0 + 8) * N + c0] = v1;
            }
        }
    }
}

// ---------------- RoPE -> split bf16 ----------------------------------------
// Q: pre-scaled by 1/sqrt(HD), layout [b*NH+h][s][KP] packed pairs.
__global__ void rope_q_split(const float* __restrict__ Q,
                             const float* __restrict__ fc, const float* __restrict__ fs,
                             uint32_t* __restrict__ qh, uint32_t* __restrict__ ql)
{
    int idx = blockIdx.x * blockDim.x + threadIdx.x;
    const int total = BSZ * NH * SEQ * KP;
    if (idx >= total) return;
    int i = idx % KP;
    int s = (idx / KP) % SEQ;
    int h = (idx / (KP * SEQ)) % NH;
    int b = idx / (KP * SEQ * NH);

    size_t base = (size_t)(b * SEQ + s) * DIMC + h * HD;
    float q0 = Q[base + 2 * i];
    float q1 = Q[base + 2 * i + 1];
    float c = fc[s * KP + i];
    float sn = fs[s * KP + i];
    const float scale = 0.083333333333333329f;
    float y0 = (q0 * c - q1 * sn) * scale;
    float y1 = (q0 * sn + q1 * c) * scale;
    split2(y0, y1, qh[idx], ql[idx]);
}

__global__ void rope_k_split(const float* __restrict__ KV,
                             const float* __restrict__ fc, const float* __restrict__ fs,
                             uint32_t* __restrict__ kh, uint32_t* __restrict__ kl)
{
    int idx = blockIdx.x * blockDim.x + threadIdx.x;
    const int total = BSZ * KVH * SEQ * KP;
    if (idx >= total) return;
    int i = idx % KP;
    int s = (idx / KP) % SEQ;
    int kvh = (idx / (KP * SEQ)) % KVH;
    int b = idx / (KP * SEQ * KVH);

    size_t base = (size_t)(b * SEQ + s) * KVOUT + kvh * HD;
    float k0 = KV[base + 2 * i];
    float k1 = KV[base + 2 * i + 1];
    float c = fc[s * KP + i];
    float sn = fs[s * KP + i];
    float y0 = k0 * c - k1 * sn;
    float y1 = k0 * sn + k1 * c;
    split2(y0, y1, kh[idx], kl[idx]);
}

// V transpose + split: out [b*KVH+kvh][d][sp] with pairs along s.
__global__ void v_trans_split(const float* __restrict__ KV,
                              uint32_t* __restrict__ vh, uint32_t* __restrict__ vl)
{
    __shared__ float tile[64][HD + 1];
    const int st = blockIdx.x;          // s tile (64)
    const int bk = blockIdx.y;          // b*KVH + kvh
    const int b = bk / KVH, kvh = bk % KVH;
    const int tid = threadIdx.x;

    const float* src = KV + (size_t)(b * SEQ + st * 64) * KVOUT + KVH * HD + kvh * HD;
    for (int e = tid; e < 64 * HD; e += 256) {
        int r = e / HD, c = e % HD;
        tile[r][c] = src[(size_t)r * KVOUT + c];
    }
    __syncthreads();

    uint32_t* oh = vh + ((size_t)bk * HD) * TPH + st * 32;
    uint32_t* ol = vl + ((size_t)bk * HD) * TPH + st * 32;
    for (int e = tid; e < HD * 32; e += 256) {
        int d = e / 32, sp = e % 32;
        uint32_t h, l;
        split2(tile[2 * sp][d], tile[2 * sp + 1][d], h, l);
        oh[(size_t)d * TPH + sp] = h;
        ol[(size_t)d * TPH + sp] = l;
    }
}

// ---------------- Flash attention (split-bf16 tensor cores) -----------------
// CTA: 128 queries x full KV; 8 warps, warp = 16 query rows. K tile 64 keys.
#define QS 76   // smem stride (uint32 pairs) for Q
#define KS 76   // for K
#define VS 36   // for V^T (t-pairs)

#define FLASH_SMEM ((2*128*QS + 2*64*KS + 2*HD*VS) * (int)sizeof(uint32_t))

__global__ __launch_bounds__(256, 1)
void flash_mma(const uint32_t* __restrict__ qh, const uint32_t* __restrict__ ql,
               const uint32_t* __restrict__ kh, const uint32_t* __restrict__ kl,
               const uint32_t* __restrict__ vh, const uint32_t* __restrict__ vl,
               float* __restrict__ out)
{
    extern __shared__ uint32_t smem[];
    uint32_t* sQh = smem;
    uint32_t* sQl = sQh + 128 * QS;
    uint32_t* sKh = sQl + 128 * QS;
    uint32_t* sKl = sKh + 64 * KS;
    uint32_t* sVh = sKl + 64 * KS;
    uint32_t* sVl = sVh + HD * VS;

    const int qt = (gridDim.x - 1) - blockIdx.x;  // heavy tiles first
    const int bh = blockIdx.y;
    const int b = bh >> 3;
    const int h = bh & 7;
    const int kvh = h >> 2;
    const int bk = b * KVH + kvh;

    const int tid = threadIdx.x;
    const int warp = tid >> 5, lane = tid & 31;
    const int lr = lane >> 2, lc = lane & 3;
    const int wm = warp * 16;

    // load Q tile (128 x 72 pairs, hi+lo)
    {
        const uint32_t* gqh = qh + ((size_t)bh * SEQ + qt * 128) * KP;
        const uint32_t* gql = ql + ((size_t)bh * SEQ + qt * 128) * KP;
        for (int e = tid; e < 128 * 18; e += 256) {
            int r = e / 18, c = (e % 18) * 4;
            *(uint4*)&sQh[r * QS + c] = *(const uint4*)&gqh[(size_t)r * KP + c];
            *(uint4*)&sQl[r * QS + c] = *(const uint4*)&gql[(size_t)r * KP + c];
        }
    }

    float o[18][4];
#pragma unroll
    for (int n = 0; n < 18; n++)
#pragma unroll
        for (int t = 0; t < 4; t++) o[n][t] = 0.f;
    float m0 = -1e30f, m1 = -1e30f, l0 = 0.f, l1 = 0.f;

    const int ktmax = 2 * qt + 1;
    const int qrow0 = qt * 128 + wm;      // warp's first query row

    for (int kt = 0; kt <= ktmax; kt++) {
        __syncthreads();
        // load K tile (64 x 72 pairs) and V^T tile (144 x 32 pairs)
        {
            const uint32_t* gkh = kh + ((size_t)bk * SEQ + kt * 64) * KP;
            const uint32_t* gkl = kl + ((size_t)bk * SEQ + kt * 64) * KP;
            for (int e = tid; e < 64 * 18; e += 256) {
                int r = e / 18, c = (e % 18) * 4;
                *(uint4*)&sKh[r * KS + c] = *(const uint4*)&gkh[(size_t)r * KP + c];
                *(uint4*)&sKl[r * KS + c] = *(const uint4*)&gkl[(size_t)r * KP + c];
            }
            const uint32_t* gvh = vh + (size_t)bk * HD * TPH + kt * 32;
            const uint32_t* gvl = vl + (size_t)bk * HD * TPH + kt * 32;
            for (int e = tid; e < HD * 8; e += 256) {
                int r = e / 8, c = (e % 8) * 4;
                *(uint4*)&sVh[r * VS + c] = *(const uint4*)&gvh[(size_t)r * TPH + c];
                *(uint4*)&sVl[r * VS + c] = *(const uint4*)&gvl[(size_t)r * TPH + c];
            }
        }
        __syncthreads();

        // ---- S = Q K^T (16 x 64 per warp) ----
        float sfr[8][4];
#pragma unroll
        for (int j = 0; j < 8; j++)
#pragma unroll
            for (int t = 0; t < 4; t++) sfr[j][t] = 0.f;

#pragma unroll
        for (int kc = 0; kc < 9; kc++) {
            uint32_t ah[4], al[4];
            int ra = (wm + lr) * QS + kc * 8 + lc;
            int rb = (wm + lr + 8) * QS + kc * 8 + lc;
            ah[0] = sQh[ra];     ah[1] = sQh[rb];
            ah[2] = sQh[ra + 4]; ah[3] = sQh[rb + 4];
            al[0] = sQl[ra];     al[1] = sQl[rb];
            al[2] = sQl[ra + 4]; al[3] = sQl[rb + 4];
#pragma unroll
            for (int j = 0; j < 8; j++) {
                int rk = (j * 8 + lr) * KS + kc * 8 + lc;
                uint32_t bh2[2] = { sKh[rk], sKh[rk + 4] };
                uint32_t bl2[2] = { sKl[rk], sKl[rk + 4] };
                mma16816(sfr[j], ah, bh2);
                mma16816(sfr[j], ah, bl2);
                mma16816(sfr[j], al, bh2);
            }
        }

        // ---- causal mask ----
        if (kt * 64 + 63 > qrow0) {
            int key0 = kt * 64;
#pragma unroll
            for (int j = 0; j < 8; j++) {
                int kc0 = key0 + j * 8 + 2 * lc;
                if (kc0     > qrow0 + lr)     sfr[j][0] = -1e9f;
                if (kc0 + 1 > qrow0 + lr)     sfr[j][1] = -1e9f;
                if (kc0     > qrow0 + lr + 8) sfr[j][2] = -1e9f;
                if (kc0 + 1 > qrow0 + lr + 8) sfr[j][3] = -1e9f;
            }
        }

        // ---- online softmax ----
        float mx0 = -1e30f, mx1 = -1e30f;
#pragma unroll
        for (int j = 0; j < 8; j++) {
            mx0 = fmaxf(mx0, fmaxf(sfr[j][0], sfr[j][1]));
            mx1 = fmaxf(mx1, fmaxf(sfr[j][2], sfr[j][3]));
        }
#pragma unroll
        for (int off = 1; off < 4; off <<= 1) {
            mx0 = fmaxf(mx0, __shfl_xor_sync(0xffffffffu, mx0, off));
            mx1 = fmaxf(mx1, __shfl_xor_sync(0xffffffffu, mx1, off));
        }
        float mn0 = fmaxf(m0, mx0), mn1 = fmaxf(m1, mx1);
        float c0 = __expf(m0 - mn0), c1 = __expf(m1 - mn1);
        m0 = mn0; m1 = mn1;

        float s0 = 0.f, s1 = 0.f;
#pragma unroll
        for (int j = 0; j < 8; j++) {
            sfr[j][0] = __expf(sfr[j][0] - m0);
            sfr[j][1] = __expf(sfr[j][1] - m0);
            sfr[j][2] = __expf(sfr[j][2] - m1);
            sfr[j][3] = __expf(sfr[j][3] - m1);
            s0 += sfr[j][0] + sfr[j][1];
            s1 += sfr[j][2] + sfr[j][3];
        }
#pragma unroll
        for (int off = 1; off < 4; off <<= 1) {
            s0 += __shfl_xor_sync(0xffffffffu, s0, off);
            s1 += __shfl_xor_sync(0xffffffffu, s1, off);
        }
        l0 = l0 * c0 + s0;
        l1 = l1 * c1 + s1;

#pragma unroll
        for (int n = 0; n < 18; n++) {
            o[n][0] *= c0; o[n][1] *= c0;
            o[n][2] *= c1; o[n][3] *= c1;
        }

        // ---- P -> bf16 hi/lo fragments (registers only) ----
        uint32_t ph01[8], ph23[8], pl01[8], pl23[8];
#pragma unroll
        for (int j = 0; j < 8; j++) {
            split2(sfr[j][0], sfr[j][1], ph01[j], pl01[j]);
            split2(sfr[j][2], sfr[j][3], ph23[j], pl23[j]);
        }

        // ---- O += P V ----
#pragma unroll
        for (int kc = 0; kc < 4; kc++) {
            uint32_t ah[4] = { ph01[2*kc], ph23[2*kc], ph01[2*kc+1], ph23[2*kc+1] };
            uint32_t al[4] = { pl01[2*kc], pl23[2*kc], pl01[2*kc+1], pl23[2*kc+1] };
#pragma unroll
            for (int n = 0; n < 18; n++) {
                int rv = (n * 8 + lr) * VS + kc * 8 + lc;
                uint32_t bh2[2] = { sVh[rv], sVh[rv + 4] };
                uint32_t bl2[2] = { sVl[rv], sVl[rv + 4] };
                mma16816(o[n], ah, bh2);
                mma16816(o[n], ah, bl2);
                mma16816(o[n], al, bh2);
            }
        }
    }

    // ---- epilogue ----
    float inv0 = 1.f / l0, inv1 = 1.f / l1;
    int r0 = qt * 128 + wm + lr;
    float* orow0 = out + ((size_t)b * SEQ + r0)     * DIMC + h * HD;
    float* orow1 = out + ((size_t)b * SEQ + r0 + 8) * DIMC + h * HD;
#pragma unroll
    for (int n = 0; n < 18; n++) {
        int col = n * 8 + 2 * lc;
        *(float2*)&orow0[col] = make_float2(o[n][0] * inv0, o[n][1] * inv0);
        *(float2*)&orow1[col] = make_float2(o[n][2] * inv1, o[n][3] * inv1);
    }
}

// ---------------- launcher --------------------------------------------------
extern "C" void kernel_launch(void* const* d_in, const int* in_sizes, int n_in,
                              void* d_out, int out_size)
{
    const float* x   = (const float*)d_in[0];
    const float* wq  = (const float*)d_in[1];
    const float* bq  = (const float*)d_in[2];
    const float* wkv = (const float*)d_in[3];
    const float* bkv = (const float*)d_in[4];
    const float* wo  = (const float*)d_in[5];
    const float* bo  = (const float*)d_in[6];
    const float* fc  = (const float*)d_in[7];
    const float* fs  = (const float*)d_in[8];
    float* out = (float*)d_out;

    float *gq, *gkv, *gat;
    uint32_t *xh, *xl, *wqh, *wql, *wkh, *wkl, *woh, *wol, *ah, *al;
    uint32_t *qh, *ql, *kh, *kl, *vh, *vl;
    cudaGetSymbolAddress((void**)&gq,  g_q);
    cudaGetSymbolAddress((void**)&gkv, g_kv);
    cudaGetSymbolAddress((void**)&gat, g_attn);
    cudaGetSymbolAddress((void**)&xh,  g_xh);
    cudaGetSymbolAddress((void**)&xl,  g_xl);
    cudaGetSymbolAddress((void**)&wqh, g_wqh);
    cudaGetSymbolAddress((void**)&wql, g_wql);
    cudaGetSymbolAddress((void**)&wkh, g_wkh);
    cudaGetSymbolAddress((void**)&wkl, g_wkl);
    cudaGetSymbolAddress((void**)&woh, g_woh);
    cudaGetSymbolAddress((void**)&wol, g_wol);
    cudaGetSymbolAddress((void**)&ah,  g_ah);
    cudaGetSymbolAddress((void**)&al,  g_al);
    cudaGetSymbolAddress((void**)&qh,  g_qh);
    cudaGetSymbolAddress((void**)&ql,  g_ql);
    cudaGetSymbolAddress((void**)&kh,  g_kh);
    cudaGetSymbolAddress((void**)&kl,  g_kl);
    cudaGetSymbolAddress((void**)&vh,  g_vh);
    cudaGetSymbolAddress((void**)&vl,  g_vl);

    cudaFuncSetAttribute(flash_mma, cudaFuncAttributeMaxDynamicSharedMemorySize,
                         FLASH_SMEM);

    // split GEMM inputs
    {
        int nx = MROWS * K2DIM;
        split_bf16<<<(nx + 255) / 256, 256>>>(x, xh, xl, nx);
        int nq = DIMC * K2DIM;
        split_bf16<<<(nq + 255) / 256, 256>>>(wq, wqh, wql, nq);
        int nk = KVOUT * K2DIM;
        split_bf16<<<(nk + 255) / 256, 256>>>(wkv, wkh, wkl, nk);
        split_bf16<<<(nq + 255) / 256, 256>>>(wo, woh, wol, nq);
    }

    // projections
    gemm_bf3<<<dim3(DIMC / 128, MROWS / 128), 256>>>(xh, xl, wqh, wql, bq, gq,
                                                     MROWS, DIMC, K2DIM);
    gemm_bf3<<<dim3((KVOUT + 127) / 128, MROWS / 128), 256>>>(xh, xl, wkh, wkl, bkv, gkv,
                                                              MROWS, KVOUT, K2DIM);

    // RoPE + split + V transpose
    {
        int tq = BSZ * NH * SEQ * KP;
        rope_q_split<<<(tq + 255) / 256, 256>>>(gq, fc, fs, qh, ql);
        int tk = BSZ * KVH * SEQ * KP;
        rope_k_split<<<(tk + 255) / 256, 256>>>(gkv, fc, fs, kh, kl);
        v_trans_split<<<dim3(SEQ / 64, BSZ * KVH), 256>>>(gkv, vh, vl);
    }

    // attention (tensor cores)
    flash_mma<<<dim3(SEQ / 128, BSZ * NH), 256, FLASH_SMEM>>>(qh, ql, kh, kl, vh, vl, gat);

    // output projection
    {
        int na = MROWS * K2DIM;
        split_bf16<<<(na + 255) / 256, 256>>>(gat, ah, al, na);
    }
    gemm_bf3<<<dim3(DIMC / 128, MROWS / 128), 256>>>(ah, al, woh, wol, bo, out,
                                                     MROWS, DIMC, K2DIM);
}

// round 5
// speedup vs baseline: 2.4805x; 1.0505x over previous
#include <cuda_runtime.h>
#include <cuda_bf16.h>
#include <math.h>
#include <stdint.h>

// Problem constants
#define DIMC   1152
#define NH     8
#define KVH    2
#define HD     144
#define BSZ    4
#define SEQ    2048
#define MROWS  (BSZ*SEQ)          // 8192
#define KVOUT  (2*KVH*HD)         // 576
#define HALF   (HD/2)             // 72
#define K2DIM  (DIMC/2)           // 576
#define KP     72                 // bf16x2 pairs per head row
#define TPH    (SEQ/2)            // seq pairs for V^T

// ---------------- scratch (device globals) ----------------------------------
__device__ float g_q   [(size_t)MROWS * DIMC];
__device__ float g_kv  [(size_t)MROWS * KVOUT];
__device__ float g_attn[(size_t)MROWS * DIMC];

// GEMM operand splits (packed bf16x2 == row-major bf16)
__device__ uint32_t g_xh [(size_t)MROWS * K2DIM];
__device__ uint32_t g_xl [(size_t)MROWS * K2DIM];
__device__ uint32_t g_wqh[(size_t)DIMC  * K2DIM];
__device__ uint32_t g_wql[(size_t)DIMC  * K2DIM];
__device__ uint32_t g_wkh[(size_t)KVOUT * K2DIM];
__device__ uint32_t g_wkl[(size_t)KVOUT * K2DIM];
__device__ uint32_t g_woh[(size_t)DIMC  * K2DIM];
__device__ uint32_t g_wol[(size_t)DIMC  * K2DIM];
__device__ uint32_t g_ah [(size_t)MROWS * K2DIM];
__device__ uint32_t g_al [(size_t)MROWS * K2DIM];

// attention operand splits (packed bf16x2)
__device__ uint32_t g_qh[(size_t)BSZ*NH *SEQ*KP];
__device__ uint32_t g_ql[(size_t)BSZ*NH *SEQ*KP];
__device__ uint32_t g_kh[(size_t)BSZ*KVH*SEQ*KP];
__device__ uint32_t g_kl[(size_t)BSZ*KVH*SEQ*KP];
__device__ uint32_t g_vh[(size_t)BSZ*KVH*HD*TPH];   // V^T, pairs along s
__device__ uint32_t g_vl[(size_t)BSZ*KVH*HD*TPH];

// ---------------- helpers ----------------------------------------------------
__device__ __forceinline__ uint32_t smem_u32(const void* p) {
    uint32_t a;
    asm("{ .reg .u64 t; cvta.to.shared.u64 t, %1; cvt.u32.u64 %0, t; }"
        : "=r"(a) : "l"(p));
    return a;
}

__device__ __forceinline__ void split2(float x, float y, uint32_t& hi, uint32_t& lo)
{
    __nv_bfloat162 h = __floats2bfloat162_rn(x, y);
    float hx = __bfloat162float(h.x), hy = __bfloat162float(h.y);
    __nv_bfloat162 l = __floats2bfloat162_rn(x - hx, y - hy);
    hi = *reinterpret_cast<uint32_t*>(&h);
    lo = *reinterpret_cast<uint32_t*>(&l);
}

__device__ __forceinline__ void mma16816(float* c, const uint32_t* a, const uint32_t* b)
{
    asm volatile(
        "mma.sync.aligned.m16n8k16.row.col.f32.bf16.bf16.f32 "
        "{%0,%1,%2,%3}, {%4,%5,%6,%7}, {%8,%9}, {%0,%1,%2,%3};\n"
        : "+f"(c[0]), "+f"(c[1]), "+f"(c[2]), "+f"(c[3])
        : "r"(a[0]), "r"(a[1]), "r"(a[2]), "r"(a[3]), "r"(b[0]), "r"(b[1]));
}

__device__ __forceinline__ void ldsm4(uint32_t& r0, uint32_t& r1, uint32_t& r2,
                                      uint32_t& r3, uint32_t a)
{
    asm volatile("ldmatrix.sync.aligned.m8n8.x4.shared.b16 {%0,%1,%2,%3}, [%4];"
                 : "=r"(r0), "=r"(r1), "=r"(r2), "=r"(r3) : "r"(a));
}

#define CP_ASYNC16(sa, gp) \
    asm volatile("cp.async.cg.shared.global [%0], [%1], 16;" :: "r"(sa), "l"(gp))
#define CP_COMMIT() asm volatile("cp.async.commit_group;" ::: "memory")
#define CP_WAIT1()  asm volatile("cp.async.wait_group 1;" ::: "memory")
#define CP_WAIT0()  asm volatile("cp.async.wait_group 0;" ::: "memory")

// ---------------- fp32 -> (hi, lo) packed bf16x2 ----------------------------
__global__ void split_bf16(const float* __restrict__ src,
                           uint32_t* __restrict__ hi, uint32_t* __restrict__ lo,
                           int n2)
{
    int i = blockIdx.x * blockDim.x + threadIdx.x;
    if (i >= n2) return;
    float2 v = ((const float2*)src)[i];
    split2(v.x, v.y, hi[i], lo[i]);
}

// ---------------- split-bf16 GEMM (ldmatrix + cp.async pipeline) -------------
// C[M,N] = A[M,K]@B[N,K]^T + bias. Tiles: CTA 128x128, K chunk = 32 bf16.
// smem row = 32 bf16 (64 B data) padded to 80 B -> conflict-free ldmatrix.
#define GB_ROWB 80                    // bytes per smem row
#define GB_ARR  (128 * GB_ROWB)       // 10240 B per array
#define GB_BUF  (4 * GB_ARR)          // Ah, Al, Bh, Bl
#define GB_SMEM (2 * GB_BUF)          // 81920 B

__global__ __launch_bounds__(256, 2)
void gemm_ldsm(const uint32_t* __restrict__ Ahg, const uint32_t* __restrict__ Alg,
               const uint32_t* __restrict__ Bhg, const uint32_t* __restrict__ Blg,
               const float* __restrict__ bias, float* __restrict__ C,
               int M, int N, int K2)
{
    extern __shared__ char smem[];
    const uint32_t sbase = smem_u32(smem);
    const int tid = threadIdx.x;
    const int warp = tid >> 5, lane = tid & 31;
    const int wm = (warp & 1) * 64;
    const int wn = (warp >> 1) * 32;
    const int m0 = blockIdx.y * 128;
    const int n0 = blockIdx.x * 128;
    const int nch = K2 / 16;          // chunks of 32 bf16 = 16 uint32

    // staging: thread -> (row = tid/4 and +64, 16B chunk = tid%4)
    const int srow = tid >> 2;
    const int schk = tid & 3;
    const int br0 = (n0 + srow     < N) ? n0 + srow      : N - 1;
    const int br1 = (n0 + srow + 64 < N) ? n0 + srow + 64 : N - 1;

    float acc[4][4][4];
#pragma unroll
    for (int i = 0; i < 4; i++)
#pragma unroll
        for (int j = 0; j < 4; j++)
#pragma unroll
            for (int t = 0; t < 4; t++) acc[i][j][t] = 0.f;

    // ldmatrix lane addressing: rows base + (lane&15), chunk sel = lane>>4
    const int lrow = lane & 15;
    const int lch = lane >> 4;        // 0 or 1

#define GB_ISSUE(ch) do { \
    const int _buf = (ch) & 1; \
    const uint32_t _sb = sbase + _buf * GB_BUF; \
    const size_t _kc = (size_t)(ch) * 16 + schk * 4; \
    uint32_t _so0 = _sb + srow * GB_ROWB + schk * 16; \
    uint32_t _so1 = _sb + (srow + 64) * GB_ROWB + schk * 16; \
    CP_ASYNC16(_so0,              Ahg + (size_t)(m0 + srow) * K2 + _kc); \
    CP_ASYNC16(_so1,              Ahg + (size_t)(m0 + srow + 64) * K2 + _kc); \
    CP_ASYNC16(_so0 + GB_ARR,     Alg + (size_t)(m0 + srow) * K2 + _kc); \
    CP_ASYNC16(_so1 + GB_ARR,     Alg + (size_t)(m0 + srow + 64) * K2 + _kc); \
    CP_ASYNC16(_so0 + 2*GB_ARR,   Bhg + (size_t)br0 * K2 + _kc); \
    CP_ASYNC16(_so1 + 2*GB_ARR,   Bhg + (size_t)br1 * K2 + _kc); \
    CP_ASYNC16(_so0 + 3*GB_ARR,   Blg + (size_t)br0 * K2 + _kc); \
    CP_ASYNC16(_so1 + 3*GB_ARR,   Blg + (size_t)br1 * K2 + _kc); \
} while (0)

    GB_ISSUE(0); CP_COMMIT();

    for (int ch = 0; ch < nch; ch++) {
        if (ch + 1 < nch) { GB_ISSUE(ch + 1); CP_COMMIT(); CP_WAIT1(); }
        else              { CP_WAIT0(); }
        __syncthreads();

        const uint32_t sb = sbase + (ch & 1) * GB_BUF;
        // per-lane base addresses (chunk kk adds 32 B, i adds 16*GB_ROWB)
        const uint32_t aH = sb + (wm + lrow) * GB_ROWB + lch * 16;
        const uint32_t aL = aH + GB_ARR;
        const uint32_t bH = sb + 2 * GB_ARR + (wn + lrow) * GB_ROWB + lch * 16;
        const uint32_t bL = bH + GB_ARR;

#pragma unroll
        for (int kk = 0; kk < 2; kk++) {
            // B fragments: j = 0..3 (each 8 cols); x4 covers two j at once
            uint32_t bh[4][2], bl[4][2];
#pragma unroll
            for (int jj = 0; jj < 2; jj++) {
                uint32_t r0, r1, r2, r3;
                ldsm4(r0, r1, r2, r3, bH + jj * (16 * GB_ROWB) + kk * 32);
                bh[2*jj][0] = r0; bh[2*jj][1] = r2;
                bh[2*jj+1][0] = r1; bh[2*jj+1][1] = r3;
                ldsm4(r0, r1, r2, r3, bL + jj * (16 * GB_ROWB) + kk * 32);
                bl[2*jj][0] = r0; bl[2*jj][1] = r2;
                bl[2*jj+1][0] = r1; bl[2*jj+1][1] = r3;
            }
#pragma unroll
            for (int i = 0; i < 4; i++) {
                uint32_t ah[4], al[4];
                ldsm4(ah[0], ah[1], ah[2], ah[3], aH + i * (16 * GB_ROWB) + kk * 32);
                ldsm4(al[0], al[1], al[2], al[3], aL + i * (16 * GB_ROWB) + kk * 32);
#pragma unroll
                for (int j = 0; j < 4; j++) {
                    mma16816(acc[i][j], ah, bh[j]);
                    mma16816(acc[i][j], ah, bl[j]);
                    mma16816(acc[i][j], al, bh[j]);
                }
            }
        }
        __syncthreads();
    }

    // epilogue
    const int lr = lane >> 2, lc = lane & 3;
#pragma unroll
    for (int i = 0; i < 4; i++) {
        int r0 = m0 + wm + i * 16 + lr;
#pragma unroll
        for (int j = 0; j < 4; j++) {
            int c0 = n0 + wn + j * 8 + lc * 2;
            if (c0 < N) {
                float2 bb = *(const float2*)&bias[c0];
                *(float2*)&C[(size_t)r0 * N + c0] =
                    make_float2(acc[i][j][0] + bb.x, acc[i][j][1] + bb.y);
                *(float2*)&C[(size_t)(r0 + 8) * N + c0] =
                    make_float2(acc[i][j][2] + bb.x, acc[i][j][3] + bb.y);
            }
        }
    }
#undef GB_ISSUE
}

// ---------------- RoPE -> split bf16 ----------------------------------------
__global__ void rope_q_split(const float* __restrict__ Q,
                             const float* __restrict__ fc, const float* __restrict__ fs,
                             uint32_t* __restrict__ qh, uint32_t* __restrict__ ql)
{
    int idx = blockIdx.x * blockDim.x + threadIdx.x;
    const int total = BSZ * NH * SEQ * KP;
    if (idx >= total) return;
    int i = idx % KP;
    int s = (idx / KP) % SEQ;
    int h = (idx / (KP * SEQ)) % NH;
    int b = idx / (KP * SEQ * NH);

    size_t base = (size_t)(b * SEQ + s) * DIMC + h * HD;
    float q0 = Q[base + 2 * i];
    float q1 = Q[base + 2 * i + 1];
    float c = fc[s * KP + i];
    float sn = fs[s * KP + i];
    const float scale = 0.083333333333333329f;
    float y0 = (q0 * c - q1 * sn) * scale;
    float y1 = (q0 * sn + q1 * c) * scale;
    split2(y0, y1, qh[idx], ql[idx]);
}

__global__ void rope_k_split(const float* __restrict__ KV,
                             const float* __restrict__ fc, const float* __restrict__ fs,
                             uint32_t* __restrict__ kh, uint32_t* __restrict__ kl)
{
    int idx = blockIdx.x * blockDim.x + threadIdx.x;
    const int total = BSZ * KVH * SEQ * KP;
    if (idx >= total) return;
    int i = idx % KP;
    int s = (idx / KP) % SEQ;
    int kvh = (idx / (KP * SEQ)) % KVH;
    int b = idx / (KP * SEQ * KVH);

    size_t base = (size_t)(b * SEQ + s) * KVOUT + kvh * HD;
    float k0 = KV[base + 2 * i];
    float k1 = KV[base + 2 * i + 1];
    float c = fc[s * KP + i];
    float sn = fs[s * KP + i];
    float y0 = k0 * c - k1 * sn;
    float y1 = k0 * sn + k1 * c;
    split2(y0, y1, kh[idx], kl[idx]);
}

// V transpose + split: out [b*KVH+kvh][d][sp] with pairs along s.
__global__ void v_trans_split(const float* __restrict__ KV,
                              uint32_t* __restrict__ vh, uint32_t* __restrict__ vl)
{
    __shared__ float tile[64][HD + 1];
    const int st = blockIdx.x;
    const int bk = blockIdx.y;
    const int b = bk / KVH, kvh = bk % KVH;
    const int tid = threadIdx.x;

    const float* src = KV + (size_t)(b * SEQ + st * 64) * KVOUT + KVH * HD + kvh * HD;
    for (int e = tid; e < 64 * HD; e += 256) {
        int r = e / HD, c = e % HD;
        tile[r][c] = src[(size_t)r * KVOUT + c];
    }
    __syncthreads();

    uint32_t* oh = vh + ((size_t)bk * HD) * TPH + st * 32;
    uint32_t* ol = vl + ((size_t)bk * HD) * TPH + st * 32;
    for (int e = tid; e < HD * 32; e += 256) {
        int d = e / 32, sp = e % 32;
        uint32_t h, l;
        split2(tile[2 * sp][d], tile[2 * sp + 1][d], h, l);
        oh[(size_t)d * TPH + sp] = h;
        ol[(size_t)d * TPH + sp] = l;
    }
}

// ---------------- Flash attention (split-bf16 mma.sync) ---------------------
#define QS 76
#define KS 76
#define VS 36

#define FLASH_SMEM ((2*128*QS + 2*64*KS + 2*HD*VS) * (int)sizeof(uint32_t))

__global__ __launch_bounds__(256, 1)
void flash_mma(const uint32_t* __restrict__ qh, const uint32_t* __restrict__ ql,
               const uint32_t* __restrict__ kh, const uint32_t* __restrict__ kl,
               const uint32_t* __restrict__ vh, const uint32_t* __restrict__ vl,
               float* __restrict__ out)
{
    extern __shared__ uint32_t fsm[];
    uint32_t* sQh = fsm;
    uint32_t* sQl = sQh + 128 * QS;
    uint32_t* sKh = sQl + 128 * QS;
    uint32_t* sKl = sKh + 64 * KS;
    uint32_t* sVh = sKl + 64 * KS;
    uint32_t* sVl = sVh + HD * VS;

    const int qt = (gridDim.x - 1) - blockIdx.x;
    const int bh = blockIdx.y;
    const int b = bh >> 3;
    const int h = bh & 7;
    const int kvh = h >> 2;
    const int bk = b * KVH + kvh;

    const int tid = threadIdx.x;
    const int warp = tid >> 5, lane = tid & 31;
    const int lr = lane >> 2, lc = lane & 3;
    const int wm = warp * 16;

    {
        const uint32_t* gqh = qh + ((size_t)bh * SEQ + qt * 128) * KP;
        const uint32_t* gql = ql + ((size_t)bh * SEQ + qt * 128) * KP;
        for (int e = tid; e < 128 * 18; e += 256) {
            int r = e / 18, c = (e % 18) * 4;
            *(uint4*)&sQh[r * QS + c] = *(const uint4*)&gqh[(size_t)r * KP + c];
            *(uint4*)&sQl[r * QS + c] = *(const uint4*)&gql[(size_t)r * KP + c];
        }
    }

    float o[18][4];
#pragma unroll
    for (int n = 0; n < 18; n++)
#pragma unroll
        for (int t = 0; t < 4; t++) o[n][t] = 0.f;
    float m0 = -1e30f, m1 = -1e30f, l0 = 0.f, l1 = 0.f;

    const int ktmax = 2 * qt + 1;
    const int qrow0 = qt * 128 + wm;

    for (int kt = 0; kt <= ktmax; kt++) {
        __syncthreads();
        {
            const uint32_t* gkh = kh + ((size_t)bk * SEQ + kt * 64) * KP;
            const uint32_t* gkl = kl + ((size_t)bk * SEQ + kt * 64) * KP;
            for (int e = tid; e < 64 * 18; e += 256) {
                int r = e / 18, c = (e % 18) * 4;
                *(uint4*)&sKh[r * KS + c] = *(const uint4*)&gkh[(size_t)r * KP + c];
                *(uint4*)&sKl[r * KS + c] = *(const uint4*)&gkl[(size_t)r * KP + c];
            }
            const uint32_t* gvh = vh + (size_t)bk * HD * TPH + kt * 32;
            const uint32_t* gvl = vl + (size_t)bk * HD * TPH + kt * 32;
            for (int e = tid; e < HD * 8; e += 256) {
                int r = e / 8, c = (e % 8) * 4;
                *(uint4*)&sVh[r * VS + c] = *(const uint4*)&gvh[(size_t)r * TPH + c];
                *(uint4*)&sVl[r * VS + c] = *(const uint4*)&gvl[(size_t)r * TPH + c];
            }
        }
        __syncthreads();

        float sfr[8][4];
#pragma unroll
        for (int j = 0; j < 8; j++)
#pragma unroll
            for (int t = 0; t < 4; t++) sfr[j][t] = 0.f;

#pragma unroll
        for (int kc = 0; kc < 9; kc++) {
            uint32_t ah[4], al[4];
            int ra = (wm + lr) * QS + kc * 8 + lc;
            int rb = (wm + lr + 8) * QS + kc * 8 + lc;
            ah[0] = sQh[ra];     ah[1] = sQh[rb];
            ah[2] = sQh[ra + 4]; ah[3] = sQh[rb + 4];
            al[0] = sQl[ra];     al[1] = sQl[rb];
            al[2] = sQl[ra + 4]; al[3] = sQl[rb + 4];
#pragma unroll
            for (int j = 0; j < 8; j++) {
                int rk = (j * 8 + lr) * KS + kc * 8 + lc;
                uint32_t bh2[2] = { sKh[rk], sKh[rk + 4] };
                uint32_t bl2[2] = { sKl[rk], sKl[rk + 4] };
                mma16816(sfr[j], ah, bh2);
                mma16816(sfr[j], ah, bl2);
                mma16816(sfr[j], al, bh2);
            }
        }

        if (kt * 64 + 63 > qrow0) {
            int key0 = kt * 64;
#pragma unroll
            for (int j = 0; j < 8; j++) {
                int kc0 = key0 + j * 8 + 2 * lc;
                if (kc0     > qrow0 + lr)     sfr[j][0] = -1e9f;
                if (kc0 + 1 > qrow0 + lr)     sfr[j][1] = -1e9f;
                if (kc0     > qrow0 + lr + 8) sfr[j][2] = -1e9f;
                if (kc0 + 1 > qrow0 + lr + 8) sfr[j][3] = -1e9f;
            }
        }

        float mx0 = -1e30f, mx1 = -1e30f;
#pragma unroll
        for (int j = 0; j < 8; j++) {
            mx0 = fmaxf(mx0, fmaxf(sfr[j][0], sfr[j][1]));
            mx1 = fmaxf(mx1, fmaxf(sfr[j][2], sfr[j][3]));
        }
#pragma unroll
        for (int off = 1; off < 4; off <<= 1) {
            mx0 = fmaxf(mx0, __shfl_xor_sync(0xffffffffu, mx0, off));
            mx1 = fmaxf(mx1, __shfl_xor_sync(0xffffffffu, mx1, off));
        }
        float mn0 = fmaxf(m0, mx0), mn1 = fmaxf(m1, mx1);
        float c0 = __expf(m0 - mn0), c1 = __expf(m1 - mn1);
        m0 = mn0; m1 = mn1;

        float s0 = 0.f, s1 = 0.f;
#pragma unroll
        for (int j = 0; j < 8; j++) {
            sfr[j][0] = __expf(sfr[j][0] - m0);
            sfr[j][1] = __expf(sfr[j][1] - m0);
            sfr[j][2] = __expf(sfr[j][2] - m1);
            sfr[j][3] = __expf(sfr[j][3] - m1);
            s0 += sfr[j][0] + sfr[j][1];
            s1 += sfr[j][2] + sfr[j][3];
        }
#pragma unroll
        for (int off = 1; off < 4; off <<= 1) {
            s0 += __shfl_xor_sync(0xffffffffu, s0, off);
            s1 += __shfl_xor_sync(0xffffffffu, s1, off);
        }
        l0 = l0 * c0 + s0;
        l1 = l1 * c1 + s1;

#pragma unroll
        for (int n = 0; n < 18; n++) {
            o[n][0] *= c0; o[n][1] *= c0;
            o[n][2] *= c1; o[n][3] *= c1;
        }

        uint32_t ph01[8], ph23[8], pl01[8], pl23[8];
#pragma unroll
        for (int j = 0; j < 8; j++) {
            split2(sfr[j][0], sfr[j][1], ph01[j], pl01[j]);
            split2(sfr[j][2], sfr[j][3], ph23[j], pl23[j]);
        }

#pragma unroll
        for (int kc = 0; kc < 4; kc++) {
            uint32_t ah[4] = { ph01[2*kc], ph23[2*kc], ph01[2*kc+1], ph23[2*kc+1] };
            uint32_t al[4] = { pl01[2*kc], pl23[2*kc], pl01[2*kc+1], pl23[2*kc+1] };
#pragma unroll
            for (int n = 0; n < 18; n++) {
                int rv = (n * 8 + lr) * VS + kc * 8 + lc;
                uint32_t bh2[2] = { sVh[rv], sVh[rv + 4] };
                uint32_t bl2[2] = { sVl[rv], sVl[rv + 4] };
                mma16816(o[n], ah, bh2);
                mma16816(o[n], ah, bl2);
                mma16816(o[n], al, bh2);
            }
        }
    }

    float inv0 = 1.f / l0, inv1 = 1.f / l1;
    int r0 = qt * 128 + wm + lr;
    float* orow0 = out + ((size_t)b * SEQ + r0)     * DIMC + h * HD;
    float* orow1 = out + ((size_t)b * SEQ + r0 + 8) * DIMC + h * HD;
#pragma unroll
    for (int n = 0; n < 18; n++) {
        int col = n * 8 + 2 * lc;
        *(float2*)&orow0[col] = make_float2(o[n][0] * inv0, o[n][1] * inv0);
        *(float2*)&orow1[col] = make_float2(o[n][2] * inv1, o[n][3] * inv1);
    }
}

// ---------------- launcher --------------------------------------------------
extern "C" void kernel_launch(void* const* d_in, const int* in_sizes, int n_in,
                              void* d_out, int out_size)
{
    const float* x   = (const float*)d_in[0];
    const float* wq  = (const float*)d_in[1];
    const float* bq  = (const float*)d_in[2];
    const float* wkv = (const float*)d_in[3];
    const float* bkv = (const float*)d_in[4];
    const float* wo  = (const float*)d_in[5];
    const float* bo  = (const float*)d_in[6];
    const float* fc  = (const float*)d_in[7];
    const float* fs  = (const float*)d_in[8];
    float* out = (float*)d_out;

    float *gq, *gkv, *gat;
    uint32_t *xh, *xl, *wqh, *wql, *wkh, *wkl, *woh, *wol, *ah, *al;
    uint32_t *qh, *ql, *kh, *kl, *vh, *vl;
    cudaGetSymbolAddress((void**)&gq,  g_q);
    cudaGetSymbolAddress((void**)&gkv, g_kv);
    cudaGetSymbolAddress((void**)&gat, g_attn);
    cudaGetSymbolAddress((void**)&xh,  g_xh);
    cudaGetSymbolAddress((void**)&xl,  g_xl);
    cudaGetSymbolAddress((void**)&wqh, g_wqh);
    cudaGetSymbolAddress((void**)&wql, g_wql);
    cudaGetSymbolAddress((void**)&wkh, g_wkh);
    cudaGetSymbolAddress((void**)&wkl, g_wkl);
    cudaGetSymbolAddress((void**)&woh, g_woh);
    cudaGetSymbolAddress((void**)&wol, g_wol);
    cudaGetSymbolAddress((void**)&ah,  g_ah);
    cudaGetSymbolAddress((void**)&al,  g_al);
    cudaGetSymbolAddress((void**)&qh,  g_qh);
    cudaGetSymbolAddress((void**)&ql,  g_ql);
    cudaGetSymbolAddress((void**)&kh,  g_kh);
    cudaGetSymbolAddress((void**)&kl,  g_kl);
    cudaGetSymbolAddress((void**)&vh,  g_vh);
    cudaGetSymbolAddress((void**)&vl,  g_vl);

    cudaFuncSetAttribute(flash_mma, cudaFuncAttributeMaxDynamicSharedMemorySize,
                         FLASH_SMEM);
    cudaFuncSetAttribute(gemm_ldsm, cudaFuncAttributeMaxDynamicSharedMemorySize,
                         GB_SMEM);

    // split GEMM inputs
    {
        int nx = MROWS * K2DIM;
        split_bf16<<<(nx + 255) / 256, 256>>>(x, xh, xl, nx);
        int nq = DIMC * K2DIM;
        split_bf16<<<(nq + 255) / 256, 256>>>(wq, wqh, wql, nq);
        int nk = KVOUT * K2DIM;
        split_bf16<<<(nk + 255) / 256, 256>>>(wkv, wkh, wkl, nk);
        split_bf16<<<(nq + 255) / 256, 256>>>(wo, woh, wol, nq);
    }

    // projections (ldmatrix + cp.async mma.sync GEMM)
    gemm_ldsm<<<dim3(DIMC / 128, MROWS / 128), 256, GB_SMEM>>>(
        xh, xl, wqh, wql, bq, gq, MROWS, DIMC, K2DIM);
    gemm_ldsm<<<dim3((KVOUT + 127) / 128, MROWS / 128), 256, GB_SMEM>>>(
        xh, xl, wkh, wkl, bkv, gkv, MROWS, KVOUT, K2DIM);

    // RoPE + split + V transpose
    {
        int tq = BSZ * NH * SEQ * KP;
        rope_q_split<<<(tq + 255) / 256, 256>>>(gq, fc, fs, qh, ql);
        int tk = BSZ * KVH * SEQ * KP;
        rope_k_split<<<(tk + 255) / 256, 256>>>(gkv, fc, fs, kh, kl);
        v_trans_split<<<dim3(SEQ / 64, BSZ * KVH), 256>>>(gkv, vh, vl);
    }

    // attention (mma.sync tensor cores)
    flash_mma<<<dim3(SEQ / 128, BSZ * NH), 256, FLASH_SMEM>>>(qh, ql, kh, kl, vh, vl, gat);

    // output projection
    {
        int na = MROWS * K2DIM;
        split_bf16<<<(na + 255) / 256, 256>>>(gat, ah, al, na);
    }
    gemm_ldsm<<<dim3(DIMC / 128, MROWS / 128), 256, GB_SMEM>>>(
        ah, al, woh, wol, bo, out, MROWS, DIMC, K2DIM);
}